// round 1
// baseline (speedup 1.0000x reference)
#include <cuda_runtime.h>
#include <stdint.h>

// Problem constants
#define NB 8
#define NC 512
#define NL 8192
#define NK 3
#define NW (NC*NC*NK)

// Conv tiling
#define TM 64          // C_out per CTA
#define TN 256         // positions per CTA
#define KC 16          // C_in chunk
#define NTHREADS 256

// Device scratch (allocation-free rule: __device__ globals)
__device__ float g_wq[6][NW];                 // ternary weights {-1,0,+1}, exact
__device__ float g_scale[6];                  // per-tensor absmean scale
__device__ float g_h[(size_t)NB*NC*NL];       // intermediate h (128 MB)

// ---------------------------------------------------------------------------
// Per-tensor absmean scale: fixed-order fp64 reduction in one CTA (deterministic).
__global__ void scale_kernel(const float* __restrict__ w, int idx) {
    __shared__ double sd[1024];
    double s = 0.0;
    for (int i = threadIdx.x; i < NW; i += 1024) s += (double)fabsf(w[i]);
    sd[threadIdx.x] = s;
    __syncthreads();
    for (int o = 512; o > 0; o >>= 1) {
        if (threadIdx.x < o) sd[threadIdx.x] += sd[threadIdx.x + o];
        __syncthreads();
    }
    if (threadIdx.x == 0) g_scale[idx] = (float)(sd[0] / (double)NW) + 1e-5f;
}

// Ternary quantization: t = clip(round_half_even(w/scale), -1, 1).
// __fdiv_rn keeps IEEE division even under --use_fast_math; rintf == jnp.round.
__global__ void quant_kernel(const float* __restrict__ w, int idx) {
    const float s = g_scale[idx];
    int i = blockIdx.x * blockDim.x + threadIdx.x;
    const int stride = gridDim.x * blockDim.x;
    for (; i < NW; i += stride) {
        float t = rintf(__fdiv_rn(w[i], s));
        t = fminf(1.0f, fmaxf(-1.0f, t));
        g_wq[idx][i] = t;
    }
}

// ---------------------------------------------------------------------------
// Fused conv1d (ternary weights) + epilogue.
//   MODE 0: out = lrelu(scale*acc + bias)            (writes g_h)
//   MODE 1: out = res + scale*acc + bias             (residual add)
// y[co,l] = sum_{ci,k} t[co,ci,k] * in[ci, l + DIL*(k-1)], zero-padded per batch.
template<int DIL, int MODE>
__global__ __launch_bounds__(NTHREADS)
void conv_kernel(const float* __restrict__ in,
                 const float* __restrict__ res,
                 const float* __restrict__ bias,
                 float* __restrict__ out,
                 int widx)
{
    constexpr int XW = TN + 2*DIL;            // input window incl. halo
    constexpr int XS = (XW + 7) & ~7;         // row stride, 32B aligned
    constexpr int NV = (8 + 2*DIL)/4 + 1;     // float4 loads covering thread window

    __shared__ float Wsm[TM][KC*NK];          // [co][ci*3+k]
    __shared__ __align__(16) float Xsm[KC][XS];

    const int t   = threadIdx.x;
    const int px  = t & 31;                   // position group (8 pos each)
    const int cy  = t >> 5;                   // co group (8 co each)
    const int b   = blockIdx.z;
    const int l0  = blockIdx.x * TN;
    const int co0 = blockIdx.y * TM;

    const float* __restrict__ gw = g_wq[widx];
    const float scale = g_scale[widx];

    float acc[8][8];
    #pragma unroll
    for (int i = 0; i < 8; i++)
        #pragma unroll
        for (int j = 0; j < 8; j++) acc[i][j] = 0.0f;

    for (int ci0 = 0; ci0 < NC; ci0 += KC) {
        __syncthreads();
        // Load W chunk [TM][KC*3]  (coalesced global, conflict-free stores)
        for (int i = t; i < TM*KC*NK; i += NTHREADS) {
            int co = i / (KC*NK);
            int r  = i - co*(KC*NK);
            Wsm[co][r] = gw[(co0+co)*(NC*NK) + ci0*NK + r];
        }
        // Load X chunk [KC][XW] with zero padding at sequence edges
        for (int i = t; i < KC*XW; i += NTHREADS) {
            int ci = i / XW;
            int j  = i - ci*XW;
            int l  = l0 - DIL + j;
            float v = 0.0f;
            if (l >= 0 && l < NL)
                v = in[((size_t)b*NC + (ci0+ci))*NL + l];
            Xsm[ci][j] = v;
        }
        __syncthreads();

        #pragma unroll 2
        for (int ci = 0; ci < KC; ci++) {
            // Pull this thread's x window into registers (aligned LDS.128)
            float xr[4*NV];
            const float4* xrow = reinterpret_cast<const float4*>(&Xsm[ci][0]);
            #pragma unroll
            for (int c = 0; c < NV; c++) {
                float4 v = xrow[px*2 + c];
                xr[4*c+0] = v.x; xr[4*c+1] = v.y; xr[4*c+2] = v.z; xr[4*c+3] = v.w;
            }
            #pragma unroll
            for (int k = 0; k < NK; k++) {
                #pragma unroll
                for (int ii = 0; ii < 8; ii++) {
                    float w = Wsm[cy*8+ii][ci*NK + k];  // warp-uniform broadcast
                    #pragma unroll
                    for (int jj = 0; jj < 8; jj++)
                        acc[ii][jj] = fmaf(w, xr[jj + DIL*k], acc[ii][jj]);
                }
            }
        }
    }

    // Epilogue
    const int p0 = l0 + px*8;
    #pragma unroll
    for (int ii = 0; ii < 8; ii++) {
        const int co = co0 + cy*8 + ii;
        const float bv = bias[co];
        const size_t base = ((size_t)b*NC + co)*NL + p0;
        float v[8];
        #pragma unroll
        for (int jj = 0; jj < 8; jj++) {
            float y = fmaf(acc[ii][jj], scale, bv);
            if (MODE == 0) {
                v[jj] = (y >= 0.0f) ? y : 0.1f * y;
            } else {
                v[jj] = y + res[base + jj];
            }
        }
        reinterpret_cast<float4*>(out + base)[0] = make_float4(v[0], v[1], v[2], v[3]);
        reinterpret_cast<float4*>(out + base)[1] = make_float4(v[4], v[5], v[6], v[7]);
    }
}

// ---------------------------------------------------------------------------
extern "C" void kernel_launch(void* const* d_in, const int* in_sizes, int n_in,
                              void* d_out, int out_size)
{
    (void)in_sizes; (void)n_in; (void)out_size;
    const float* x = (const float*)d_in[0];
    const float* w[6];
    const float* bs[6];
    for (int i = 0; i < 6; i++) {
        w[i]  = (const float*)d_in[1 + 2*i];
        bs[i] = (const float*)d_in[2 + 2*i];
    }
    float* out = (float*)d_out;

    float* h = nullptr;
    cudaGetSymbolAddress((void**)&h, g_h);   // pure host query, capture-safe

    // Weight quantization (deterministic, recomputed every call)
    for (int i = 0; i < 6; i++) scale_kernel<<<1, 1024>>>(w[i], i);
    for (int i = 0; i < 6; i++) quant_kernel<<<768, 256>>>(w[i], i);

    dim3 grid(NL/TN, NC/TM, NB);   // (32, 8, 8)

    // Branch 0 (dilation 1):  h = lrelu(conv(x));  out = x + conv(h)
    conv_kernel<1,0><<<grid, NTHREADS>>>(x,   nullptr, bs[0], h,   0);
    conv_kernel<1,1><<<grid, NTHREADS>>>(h,   x,       bs[1], out, 1);
    // Branch 1 (dilation 3):  in-place elementwise residual on out is per-thread safe
    conv_kernel<3,0><<<grid, NTHREADS>>>(out, nullptr, bs[2], h,   2);
    conv_kernel<1,1><<<grid, NTHREADS>>>(h,   out,     bs[3], out, 3);
    // Branch 2 (dilation 5)
    conv_kernel<5,0><<<grid, NTHREADS>>>(out, nullptr, bs[4], h,   4);
    conv_kernel<1,1><<<grid, NTHREADS>>>(h,   out,     bs[5], out, 5);
}

// round 6
// speedup vs baseline: 3.4488x; 3.4488x over previous
#include <cuda_runtime.h>
#include <stdint.h>

// Problem constants
#define NB 8
#define NC 512
#define NL 8192
#define NK 3
#define NW (NC*NC*NK)

// Conv tiling
#define TM 128         // C_out per CTA
#define TN 256         // positions per CTA
#define KC 8           // C_in per smem stage
#define NT 512         // threads per CTA (16 warps: 4 M x 4 N)

// Device scratch (allocation-free rule: __device__ globals)
__device__ float  g_wqT[6][NK][NC][NC];     // [widx][tap][ci][co], exact ternary
__device__ float  g_scale[6];
__device__ double g_part[6][96];
__device__ float  g_h[(size_t)NB*NC*NL];    // intermediate h (128 MB)

struct WPtrs { const float* w[6]; };

// ---------------------------------------------------------------------------
// Stage 1: per-slice |w| partial sums, fixed order (deterministic).
__global__ void partial_kernel(WPtrs p) {
    const int widx = blockIdx.y;
    const float* w = p.w[widx] + blockIdx.x * (NW/96);
    __shared__ double sd[256];
    double s = 0.0;
    for (int i = threadIdx.x; i < NW/96; i += 256) s += (double)fabsf(w[i]);
    sd[threadIdx.x] = s;
    __syncthreads();
    for (int o = 128; o > 0; o >>= 1) {
        if (threadIdx.x < o) sd[threadIdx.x] += sd[threadIdx.x + o];
        __syncthreads();
    }
    if (threadIdx.x == 0) g_part[widx][blockIdx.x] = sd[0];
}

// Stage 2: combine partials -> absmean scale per weight tensor.
__global__ void finalize_kernel() {
    const int i = threadIdx.x;
    if (i < 6) {
        double s = 0.0;
        for (int j = 0; j < 96; j++) s += g_part[i][j];
        g_scale[i] = (float)(s / (double)NW) + 1e-5f;
    }
}

// Ternary quantize + transpose to [tap][ci][co] (coalesced writes).
// rintf == jnp.round (half-to-even); __fdiv_rn keeps IEEE div under fast_math.
__global__ void quant_kernel(WPtrs p) {
    const int widx = blockIdx.y;
    const float* __restrict__ w = p.w[widx];
    const float s = g_scale[widx];
    float* __restrict__ dst = &g_wqT[widx][0][0][0];
    for (int o = blockIdx.x*blockDim.x + threadIdx.x; o < NW; o += gridDim.x*blockDim.x) {
        const int co  = o & (NC-1);
        const int r   = o >> 9;
        const int ci  = r & (NC-1);
        const int tap = r >> 9;
        float t = rintf(__fdiv_rn(w[co*(NC*NK) + ci*NK + tap], s));
        dst[o] = fminf(1.0f, fmaxf(-1.0f, t));
    }
}

// ---------------------------------------------------------------------------
__device__ __forceinline__ void mma_tf32(float* d, const uint32_t* a,
                                         uint32_t b0, uint32_t b1) {
    asm volatile(
        "mma.sync.aligned.m16n8k8.row.col.f32.tf32.tf32.f32 "
        "{%0,%1,%2,%3}, {%4,%5,%6,%7}, {%8,%9}, {%0,%1,%2,%3};\n"
        : "+f"(d[0]), "+f"(d[1]), "+f"(d[2]), "+f"(d[3])
        : "r"(a[0]), "r"(a[1]), "r"(a[2]), "r"(a[3]), "r"(b0), "r"(b1));
}

// Fused conv1d (ternary weights) + epilogue, implicit GEMM on tensor cores.
//   MODE 0: out = lrelu(scale*acc + bias)
//   MODE 1: out = res + scale*acc + bias
template<int DIL, int MODE>
__global__ __launch_bounds__(NT, 1)
void conv_kernel(const float* __restrict__ in,
                 const float* __restrict__ res,
                 const float* __restrict__ bias,
                 float* __restrict__ out,
                 int widx)
{
    constexpr int XW = TN + 2*DIL;                // input window incl. halo
    constexpr int XS = (XW <= 264) ? 264 : 296;   // row stride, %32 == 8 (no conflicts)
    constexpr int CS = 136;                       // Wsm co stride, %32 == 8
    constexpr int XN = KC * XW;
    constexpr int WN = NK * KC * TM;              // 3072
    constexpr int XI = (XN + NT - 1) / NT;        // 5
    constexpr int WI = WN / NT;                   // 6

    __shared__ uint32_t Xsm[KC][XS];              // tf32 bit patterns
    __shared__ float    Wsm[NK][KC][CS];          // [tap][ci][co]

    const int t    = threadIdx.x;
    const int lane = t & 31;
    const int wid  = t >> 5;
    const int wm   = wid & 3;                     // warp M index (0..3)
    const int wn   = wid >> 2;                    // warp N index (0..3)
    const int g    = lane >> 2;                   // groupID (0..7)
    const int tg   = lane & 3;                    // thread-in-group (0..3)

    const int co0 = blockIdx.x * TM;
    const int l0  = blockIdx.y * TN;
    const int b   = blockIdx.z;

    const float* __restrict__ wT = &g_wqT[widx][0][0][0];
    const size_t in_b = (size_t)b * NC * NL;

    float acc[2][8][4];
    #pragma unroll
    for (int mi = 0; mi < 2; mi++)
        #pragma unroll
        for (int ni = 0; ni < 8; ni++)
            #pragma unroll
            for (int q = 0; q < 4; q++) acc[mi][ni][q] = 0.0f;

    uint32_t xr[XI];
    float    wr[WI];

    // -------- prefetch chunk 0 --------
    #pragma unroll
    for (int it = 0; it < XI; it++) {
        const int i = t + it*NT;
        uint32_t u = 0u;
        if (i < XN) {
            const int ci = i / XW;
            const int j  = i - ci*XW;
            const int l  = l0 - DIL + j;
            float v = (l >= 0 && l < NL) ? in[in_b + (size_t)ci*NL + l] : 0.0f;
            asm("cvt.rna.tf32.f32 %0, %1;" : "=r"(u) : "f"(v));
        }
        xr[it] = u;
    }
    #pragma unroll
    for (int it = 0; it < WI; it++) {
        const int i   = t + it*NT;
        const int tap = i / (KC*TM);
        const int r   = i - tap*(KC*TM);
        const int ci  = r >> 7;
        const int co  = r & (TM-1);
        wr[it] = wT[(size_t)(tap*NC + ci)*NC + co0 + co];
    }

    const int cwb = wm * 32;
    const int pwb = wn * 64;

    for (int c = 0; c < NC/KC; c++) {
        __syncthreads();
        // regs -> smem
        #pragma unroll
        for (int it = 0; it < XI; it++) {
            const int i = t + it*NT;
            if (i < XN) { const int ci = i / XW; Xsm[ci][i - ci*XW] = xr[it]; }
        }
        #pragma unroll
        for (int it = 0; it < WI; it++) {
            const int i   = t + it*NT;
            const int tap = i / (KC*TM);
            const int r   = i - tap*(KC*TM);
            Wsm[tap][r >> 7][r & (TM-1)] = wr[it];
        }
        __syncthreads();

        // prefetch next chunk (gmem latency overlaps the mma work below)
        if (c + 1 < NC/KC) {
            const int ci0 = (c + 1) * KC;
            #pragma unroll
            for (int it = 0; it < XI; it++) {
                const int i = t + it*NT;
                uint32_t u = 0u;
                if (i < XN) {
                    const int ci = i / XW;
                    const int j  = i - ci*XW;
                    const int l  = l0 - DIL + j;
                    float v = (l >= 0 && l < NL) ? in[in_b + (size_t)(ci0+ci)*NL + l] : 0.0f;
                    asm("cvt.rna.tf32.f32 %0, %1;" : "=r"(u) : "f"(v));
                }
                xr[it] = u;
            }
            #pragma unroll
            for (int it = 0; it < WI; it++) {
                const int i   = t + it*NT;
                const int tap = i / (KC*TM);
                const int r   = i - tap*(KC*TM);
                const int ci  = r >> 7;
                const int co  = r & (TM-1);
                wr[it] = wT[(size_t)(tap*NC + ci0 + ci)*NC + co0 + co];
            }
        }

        // -------- compute: 3 taps x (2 M-tiles x 8 N-tiles) m16n8k8 --------
        #pragma unroll
        for (int tap = 0; tap < NK; tap++) {
            uint32_t a[2][4];
            #pragma unroll
            for (int mi = 0; mi < 2; mi++) {
                const int cw = cwb + mi*16 + g;
                a[mi][0] = __float_as_uint(Wsm[tap][tg  ][cw]);
                a[mi][1] = __float_as_uint(Wsm[tap][tg  ][cw+8]);
                a[mi][2] = __float_as_uint(Wsm[tap][tg+4][cw]);
                a[mi][3] = __float_as_uint(Wsm[tap][tg+4][cw+8]);
            }
            #pragma unroll
            for (int ni = 0; ni < 8; ni++) {
                const int col = pwb + ni*8 + g + tap*DIL;
                const uint32_t b0 = Xsm[tg  ][col];
                const uint32_t b1 = Xsm[tg+4][col];
                mma_tf32(acc[0][ni], a[0], b0, b1);
                mma_tf32(acc[1][ni], a[1], b0, b1);
            }
        }
    }

    // -------- epilogue --------
    const float sc = g_scale[widx];
    #pragma unroll
    for (int mi = 0; mi < 2; mi++) {
        const int co_r = co0 + cwb + mi*16 + g;
        const float bv0 = bias[co_r];
        const float bv1 = bias[co_r + 8];
        #pragma unroll
        for (int ni = 0; ni < 8; ni++) {
            const int pos = l0 + pwb + ni*8 + tg*2;
            const size_t o0 = ((size_t)b*NC + co_r) * NL + pos;
            const size_t o1 = o0 + (size_t)8 * NL;

            float y0 = fmaf(acc[mi][ni][0], sc, bv0);
            float y1 = fmaf(acc[mi][ni][1], sc, bv0);
            float y2 = fmaf(acc[mi][ni][2], sc, bv1);
            float y3 = fmaf(acc[mi][ni][3], sc, bv1);

            float2 v0, v1;
            if (MODE == 0) {
                v0.x = (y0 >= 0.0f) ? y0 : 0.1f*y0;
                v0.y = (y1 >= 0.0f) ? y1 : 0.1f*y1;
                v1.x = (y2 >= 0.0f) ? y2 : 0.1f*y2;
                v1.y = (y3 >= 0.0f) ? y3 : 0.1f*y3;
            } else {
                const float2 r0 = *reinterpret_cast<const float2*>(res + o0);
                const float2 r1 = *reinterpret_cast<const float2*>(res + o1);
                v0.x = y0 + r0.x;  v0.y = y1 + r0.y;
                v1.x = y2 + r1.x;  v1.y = y3 + r1.y;
            }
            *reinterpret_cast<float2*>(out + o0) = v0;
            *reinterpret_cast<float2*>(out + o1) = v1;
        }
    }
}

// ---------------------------------------------------------------------------
extern "C" void kernel_launch(void* const* d_in, const int* in_sizes, int n_in,
                              void* d_out, int out_size)
{
    (void)in_sizes; (void)n_in; (void)out_size;
    const float* x = (const float*)d_in[0];
    WPtrs wp;
    const float* bs[6];
    for (int i = 0; i < 6; i++) {
        wp.w[i] = (const float*)d_in[1 + 2*i];
        bs[i]   = (const float*)d_in[2 + 2*i];
    }
    float* out = (float*)d_out;

    float* h = nullptr;
    cudaGetSymbolAddress((void**)&h, g_h);  // host-side query, capture-safe

    // Weight quantization: parallel deterministic scale + quant/transpose
    partial_kernel<<<dim3(96, 6), 256>>>(wp);
    finalize_kernel<<<1, 32>>>();
    quant_kernel<<<dim3(512, 6), 256>>>(wp);

    dim3 grid(NC/TM, NL/TN, NB);   // (4, 32, 8): co-tiles fastest for L2 reuse

    // Branch 0 (dilation 1):  h = lrelu(conv(x));  out = x + conv(h)
    conv_kernel<1,0><<<grid, NT>>>(x,   nullptr, bs[0], h,   0);
    conv_kernel<1,1><<<grid, NT>>>(h,   x,       bs[1], out, 1);
    // Branch 1 (dilation 3)
    conv_kernel<3,0><<<grid, NT>>>(out, nullptr, bs[2], h,   2);
    conv_kernel<1,1><<<grid, NT>>>(h,   out,     bs[3], out, 3);
    // Branch 2 (dilation 5)
    conv_kernel<5,0><<<grid, NT>>>(out, nullptr, bs[4], h,   4);
    conv_kernel<1,1><<<grid, NT>>>(h,   out,     bs[5], out, 5);
}